// round 5
// baseline (speedup 1.0000x reference)
#include <cuda_runtime.h>
#include <math.h>

#define B 128
#define L 1024
#define NBLK (B * L / 8)      // 16384 blocks, 128 per batch
#define P_TX 10.0f
#define P_NOISE 6.2946e-14f

__device__ float g_bsum[NBLK];          // per-block partial sums of R
__device__ unsigned int g_done = 0;     // completion counter (reset by last block)

__inline__ __device__ float warp_reduce(float v) {
    #pragma unroll
    for (int o = 16; o; o >>= 1) v += __shfl_down_sync(0xffffffffu, v, o);
    return v;
}

// Single fused kernel: warp-per-row mainloop + last-block finalize tail.
__global__ void __launch_bounds__(256) fused_kernel(const float* __restrict__ H,
                                                    const float* __restrict__ prob,
                                                    float* __restrict__ out) {
    const int row  = blockIdx.x * 8 + (threadIdx.x >> 5);   // global row in [0, B*L)
    const int lane = threadIdx.x & 31;
    const int b    = blockIdx.x >> 7;                        // 128 blocks per batch
    const int k    = row & (L - 1);

    __shared__ float sPy[L];            // P * y[b, :]  (4 KB)

    // Cooperative stage of Py (coalesced stride-2 extraction, done once per block)
    const float* __restrict__ pb = prob + 2 * (size_t)b * L;
    #pragma unroll
    for (int i = 0; i < 4; i++) {
        int j = i * 256 + threadIdx.x;
        sPy[j] = P_TX * __ldg(pb + 2 * j + 1);
    }
    __syncthreads();

    const float4* __restrict__ h4 = reinterpret_cast<const float4*>(H + (size_t)row * L);
    const float4* __restrict__ s4 = reinterpret_cast<const float4*>(sPy);

    float acc = 0.0f;
    #pragma unroll
    for (int i = 0; i < 8; i++) {
        const int t = i * 32 + lane;
        float4 h = __ldg(h4 + t);
        float4 p = s4[t];               // conflict-free LDS.128
        acc = fmaf(h.x * h.x, p.x, acc);
        acc = fmaf(h.y * h.y, p.y, acc);
        acc = fmaf(h.z * h.z, p.z, acc);
        acc = fmaf(h.w * h.w, p.w, acc);
    }

    acc = warp_reduce(acc);

    __shared__ float sR[8];
    if (lane == 0) {
        float d      = __ldg(H + (size_t)row * L + k);   // H[b,k,k] (L1 hot)
        float signal = d * d * sPy[k];
        float interf = acc - signal;
        sR[threadIdx.x >> 5] =
            log1pf(signal / (interf + P_NOISE)) * 1.4426950408889634f;
    }
    __syncthreads();

    __shared__ bool sLast;
    if (threadIdx.x == 0) {
        float s = 0.0f;
        #pragma unroll
        for (int w = 0; w < 8; w++) s += sR[w];
        g_bsum[blockIdx.x] = s;
        __threadfence();                                 // partial visible before count
        unsigned int t = atomicAdd(&g_done, 1u);
        sLast = (t == (unsigned int)(NBLK - 1));
    }
    __syncthreads();

    if (!sLast) return;

    // ---- Finalize tail: last block reduces all partials (deterministic values/order) ----
    const int wid = threadIdx.x >> 5;                    // 8 warps, 16 batches each
    float inv_acc = 0.0f;
    #pragma unroll
    for (int rep = 0; rep < 16; rep++) {
        const int bidx = wid * 16 + rep;                 // batch index
        const float4* __restrict__ p =
            reinterpret_cast<const float4*>(g_bsum + bidx * 128);
        float4 v = p[lane];                              // 32 lanes * 4 = 128 partials
        float s = (v.x + v.y) + (v.z + v.w);
        s = warp_reduce(s);
        if (lane == 0) inv_acc += 1.0f / s;
    }

    __shared__ float sm[8];
    if (lane == 0) sm[wid] = inv_acc;
    __syncthreads();
    if (threadIdx.x == 0) {
        float v = 0.0f;
        #pragma unroll
        for (int w = 0; w < 8; w++) v += sm[w];
        out[0] = v * (1.0f / (float)B);
        g_done = 0;                                      // reset for next replay
    }
}

extern "C" void kernel_launch(void* const* d_in, const int* in_sizes, int n_in,
                              void* d_out, int out_size) {
    const float* prob = (const float*)d_in[0];
    const float* H    = (const float*)d_in[1];
    if (in_sizes[0] != 2 * B * L) { prob = (const float*)d_in[1]; H = (const float*)d_in[0]; }

    fused_kernel<<<NBLK, 256>>>(H, prob, (float*)d_out);
}

// round 6
// speedup vs baseline: 1.0778x; 1.0778x over previous
#include <cuda_runtime.h>
#include <math.h>

#define B 128
#define L 1024
#define NBLK (B * L / 8)      // 16384 blocks, 128 per batch
#define P_TX 10.0f
#define P_NOISE 6.2946e-14f

__device__ float g_bsum[NBLK];            // per-block partial sums of R
__device__ float g_inv[B];                // per-batch 1/sum
__device__ unsigned int g_cnt[B] = {};    // per-batch completion counters
__device__ unsigned int g_final = 0;      // final completion counter

__inline__ __device__ float warp_reduce(float v) {
    #pragma unroll
    for (int o = 16; o; o >>= 1) v += __shfl_down_sync(0xffffffffu, v, o);
    return v;
}

__device__ __forceinline__ unsigned int atom_add_acqrel(unsigned int* p) {
    unsigned int old;
    asm volatile("atom.add.acq_rel.gpu.u32 %0, [%1], 1;"
                 : "=r"(old) : "l"(p) : "memory");
    return old;
}

// Single fused kernel: warp-per-row mainloop + hierarchical fence-free finalize.
__global__ void __launch_bounds__(256) fused_kernel(const float* __restrict__ H,
                                                    const float* __restrict__ prob,
                                                    float* __restrict__ out) {
    const int row  = blockIdx.x * 8 + (threadIdx.x >> 5);   // global row in [0, B*L)
    const int lane = threadIdx.x & 31;
    const int b    = blockIdx.x >> 7;                        // 128 blocks per batch
    const int k    = row & (L - 1);

    __shared__ float sPy[L];            // P * y[b, :]  (4 KB)

    const float* __restrict__ pb = prob + 2 * (size_t)b * L;
    #pragma unroll
    for (int i = 0; i < 4; i++) {
        int j = i * 256 + threadIdx.x;
        sPy[j] = P_TX * __ldg(pb + 2 * j + 1);
    }
    __syncthreads();

    const float4* __restrict__ h4 = reinterpret_cast<const float4*>(H + (size_t)row * L);
    const float4* __restrict__ s4 = reinterpret_cast<const float4*>(sPy);

    float acc = 0.0f;
    #pragma unroll
    for (int i = 0; i < 8; i++) {
        const int t = i * 32 + lane;
        float4 h = __ldg(h4 + t);
        float4 p = s4[t];               // conflict-free LDS.128
        acc = fmaf(h.x * h.x, p.x, acc);
        acc = fmaf(h.y * h.y, p.y, acc);
        acc = fmaf(h.z * h.z, p.z, acc);
        acc = fmaf(h.w * h.w, p.w, acc);
    }

    acc = warp_reduce(acc);

    __shared__ float sR[8];
    if (lane == 0) {
        float d      = __ldg(H + (size_t)row * L + k);   // H[b,k,k] (L1 hot)
        float signal = d * d * sPy[k];
        float interf = acc - signal;
        sR[threadIdx.x >> 5] =
            log1pf(signal / (interf + P_NOISE)) * 1.4426950408889634f;
    }
    __syncthreads();

    __shared__ bool sLastInBatch;
    if (threadIdx.x == 0) {
        float s = 0.0f;
        #pragma unroll
        for (int w = 0; w < 8; w++) s += sR[w];
        __stcg(&g_bsum[blockIdx.x], s);                  // to L2 (coherence point)
        unsigned int t = atom_add_acqrel(&g_cnt[b]);     // release orders the stcg
        sLastInBatch = (t == 127u);
    }
    __syncthreads();

    if (!sLastInBatch) return;

    // ---- Per-batch tail (warp 0 of this batch's last block) ----
    if (threadIdx.x >= 32) return;

    {
        const float4* __restrict__ p =
            reinterpret_cast<const float4*>(g_bsum + b * 128);
        float4 v = __ldcg(p + lane);                     // 32 lanes * 4 = 128 partials
        float s = (v.x + v.y) + (v.z + v.w);
        s = warp_reduce(s);

        bool last_final = false;
        if (lane == 0) {
            __stcg(&g_inv[b], 1.0f / s);
            g_cnt[b] = 0;                                // reset for next replay
            unsigned int u = atom_add_acqrel(&g_final);  // release orders the stcg
            last_final = (u == (unsigned int)(B - 1));
        }
        last_final = __shfl_sync(0xffffffffu, last_final, 0);
        if (!last_final) return;
    }

    // ---- Global tail: one warp reduces 128 per-batch inverses ----
    {
        const float4* __restrict__ p = reinterpret_cast<const float4*>(g_inv);
        float4 v = __ldcg(p + lane);                     // 128 values
        float s = (v.x + v.y) + (v.z + v.w);
        s = warp_reduce(s);
        if (lane == 0) {
            out[0] = s * (1.0f / (float)B);
            g_final = 0;                                 // reset for next replay
        }
    }
}

extern "C" void kernel_launch(void* const* d_in, const int* in_sizes, int n_in,
                              void* d_out, int out_size) {
    const float* prob = (const float*)d_in[0];
    const float* H    = (const float*)d_in[1];
    if (in_sizes[0] != 2 * B * L) { prob = (const float*)d_in[1]; H = (const float*)d_in[0]; }

    fused_kernel<<<NBLK, 256>>>(H, prob, (float*)d_out);
}